// round 16
// baseline (speedup 1.0000x reference)
#include <cuda_runtime.h>
#include <cuda_bf16.h>
#include <cstdint>

// Problem constants
#define BB 2048   // batch
#define BP 2058   // padded batch (147 CTAs * 14 rows)
#define TT 64     // timesteps
#define HH 64     // LSTM hidden
#define GG 256    // 4*H gates
#define NL 8      // LSTM layers
#define BT 14     // batch rows per CTA
#define NCTA 147
#define NTHR 1024
#define RW (BT * 64)   // 896 floats per row-plane

// Ping-pong inter-layer buffers, layout [T, BP, 64] (layer0 x: cols 0-15, rest zero)
__device__ float g_bufA[(size_t)TT * BP * HH + 256];
__device__ float g_bufB[(size_t)TT * BP * HH + 256];

__device__ __forceinline__ float sigm(float x) {
    return __fdividef(1.0f, 1.0f + __expf(-x));
}
__device__ __forceinline__ float tanh_(float x) {
    return __fdividef(2.0f, 1.0f + __expf(-2.0f * x)) - 1.0f;
}

// ---- packed f32x2 helpers (Blackwell FFMA2; PTX-only) ----
__device__ __forceinline__ void ffma2(uint64_t& d, uint64_t a, uint64_t b) {
    asm("fma.rn.f32x2 %0, %1, %2, %0;" : "+l"(d) : "l"(a), "l"(b));
}
__device__ __forceinline__ uint64_t pack2(float lo, float hi) {
    uint64_t r;
    asm("mov.b64 %0, {%1, %2};" : "=l"(r) : "f"(lo), "f"(hi));
    return r;
}
__device__ __forceinline__ float hsum2(uint64_t v) {
    float lo, hi;
    asm("mov.b64 {%0, %1}, %2;" : "=f"(lo), "=f"(hi) : "l"(v));
    return lo + hi;
}
__device__ __forceinline__ void cp_async16(uint32_t dst_smem, const void* src) {
    asm volatile("cp.async.ca.shared.global [%0], [%1], 16;"
                 :: "r"(dst_smem), "l"(src) : "memory");
}

// ---------------------------------------------------------------------------
// Whole-model persistent kernel; 147 CTAs x 1024 threads; each CTA owns 14
// batch rows end-to-end. Mapping: p = tid&127 (col pair jA=p, jB=p+128),
// q = tid>>7 (8 K-windows of 16: q<4 -> x ks, q>=4 -> h ks). Weights/thread:
// 2 cols x 16 ks = 16 u64 (32 regs) -> whole kernel fits 64 regs -> 32 warps
// resident (8/SMSP) for latency hiding. Bias lives in smem (added in EW);
// x(t+2) prefetched with cp.async (no regs). Cross-step 2-barrier schedule:
//   P1: ML(t) rows 8-13  || EW(t) rows 0-7  | wait cp | bar
//   P2: ML(t+1) rows 0-7 || EW(t) rows 8-13 || cp.async x(t+2)  | bar
// ---------------------------------------------------------------------------
__global__ void __launch_bounds__(NTHR, 1)
model_kernel(const float* __restrict__ x_in,
             const float* __restrict__ w1, const float* __restrict__ b1,
             const float* __restrict__ w2, const float* __restrict__ b2,
             const float* __restrict__ w_ih0, const float* __restrict__ w_hh0,
             const float* __restrict__ b_ih0, const float* __restrict__ b_hh0,
             const float* __restrict__ w_ih, const float* __restrict__ w_hh,
             const float* __restrict__ b_ih, const float* __restrict__ b_hh,
             const float* __restrict__ wo1, const float* __restrict__ bo1,
             const float* __restrict__ wo2, const float* __restrict__ bo2,
             float* __restrict__ outp)
{
    extern __shared__ float smem[];
    float* s_x    = smem;                  // [2][RW]
    float* s_h    = s_x + 2 * RW;          // [RW]
    float* s_c    = s_h + RW;              // [RW]
    float* s_gp   = s_c + RW;              // [32][RW]  plane = gate*8+q
    float* s_bias = s_gp + 32 * RW;        // [256]
    float* s_mw   = s_bias + 256;          // mlp-in w1[32],b1[16],w2[256],b2[16]
    float* s_ow1  = s_mw + 320;            // [32][64]
    float* s_ob1  = s_ow1 + 2048;          // [32]
    float* s_ow2  = s_ob1 + 32;            // [4][32]
    float* s_ob2  = s_ow2 + 128;           // [4]

    const int tid = threadIdx.x;
    const int p   = tid & 127;             // column pair
    const int q   = tid >> 7;              // K window 0..7
    const int b0  = blockIdx.x * BT;
    const int glo = p >> 6;                // gate of jA: 0=i, 1=f
    const int u   = p & 63;                // unit

    const uint32_t sx_u32 = (uint32_t)__cvta_generic_to_shared(s_x);

    // ---- load MLP weights into smem ----
    if (tid < 32)  s_mw[tid] = w1[tid];
    if (tid < 16)  s_mw[32 + tid] = b1[tid];
    if (tid >= 64 && tid < 64 + 256) s_mw[48 + (tid - 64)] = w2[tid - 64];
    if (tid >= 320 && tid < 336) s_mw[304 + (tid - 320)] = b2[tid - 320];
    for (int i = tid; i < 2048; i += NTHR) s_ow1[i] = wo1[i];
    if (tid < 32) s_ob1[tid] = bo1[tid];
    if (tid < 128) s_ow2[tid] = wo2[tid];
    if (tid < 4) s_ob2[tid] = bo2[tid];
    __syncthreads();

    // ---- prologue: input MLP for own rows -> g_bufA[t][b0..b0+13][0..63] ----
    if (tid < BT * TT) {
        const float* mw1 = s_mw;
        const float* mb1 = s_mw + 32;
        const float* mw2 = s_mw + 48;
        const float* mb2 = s_mw + 304;
        int r = tid >> 6;
        int t = tid & 63;
        int b = b0 + r;
        float x0 = 0.f, x1 = 0.f;
        if (b < BB) {
            x0 = x_in[((size_t)b * TT + t) * 2 + 0];
            x1 = x_in[((size_t)b * TT + t) * 2 + 1];
        }
        float h1[16];
#pragma unroll
        for (int j = 0; j < 16; j++) {
            float v = fmaf(mw1[j * 2], x0, fmaf(mw1[j * 2 + 1], x1, mb1[j]));
            h1[j] = fmaxf(v, 0.0f);
        }
        float4* dst = (float4*)(g_bufA + ((size_t)t * BP + b) * 64);
#pragma unroll
        for (int j4 = 0; j4 < 4; j4++) {
            float o[4];
#pragma unroll
            for (int jj = 0; jj < 4; jj++) {
                int j = j4 * 4 + jj;
                float s = mb2[j];
#pragma unroll
                for (int k = 0; k < 16; k++) s = fmaf(mw2[j * 16 + k], h1[k], s);
                o[jj] = s;
            }
            dst[j4] = make_float4(o[0], o[1], o[2], o[3]);
        }
        float4 z = make_float4(0.f, 0.f, 0.f, 0.f);
#pragma unroll
        for (int j = 4; j < 16; j++) dst[j] = z;
    }

    // ---- layer loop ----
    int cur_in = 0;
    for (int l = 0; l < NL; l++) {
        const float* in  = cur_in ? g_bufB : g_bufA;
        float*       out = cur_in ? g_bufA : g_bufB;

        // weights: 2 cols x 16 ks (window q) as u64 pairs
        uint64_t w[2][8];
#pragma unroll
        for (int c = 0; c < 2; c++) {
            const int j = p + c * 128;
#pragma unroll
            for (int kk = 0; kk < 16; kk += 2) {
                float a, b;
                if (q < 4) {
                    int k = q * 16 + kk;
                    if (l == 0) {
                        a = (k < 16)     ? w_ih0[(size_t)j * 16 + k]     : 0.0f;
                        b = (k + 1 < 16) ? w_ih0[(size_t)j * 16 + k + 1] : 0.0f;
                    } else {
                        const float* wih = w_ih + (size_t)(l - 1) * GG * HH;
                        a = wih[(size_t)j * 64 + k];
                        b = wih[(size_t)j * 64 + k + 1];
                    }
                } else {
                    int k = (q - 4) * 16 + kk;
                    const float* whh = (l == 0) ? w_hh0 : w_hh + (size_t)(l - 1) * GG * HH;
                    a = whh[(size_t)j * 64 + k];
                    b = whh[(size_t)j * 64 + k + 1];
                }
                w[c][kk / 2] = pack2(a, b);
            }
        }
        // bias -> smem
        if (tid < GG) {
            const float* bi = (l == 0) ? b_ih0 : b_ih + (size_t)(l - 1) * GG;
            const float* bh = (l == 0) ? b_hh0 : b_hh + (size_t)(l - 1) * GG;
            s_bias[tid] = bi[tid] + bh[tid];
        }

        // partial-plane base pointers for this thread
        float* gpA = s_gp + (size_t)(glo       * 8 + q) * RW + u;
        float* gpB = s_gp + (size_t)((2 + glo) * 8 + q) * RW + u;

        // ---- ML chunk of 2 rows at rs (even) ----
        auto ml2 = [&](const float* ap, int rs) {
            uint64_t a00 = 0ull, a01 = 0ull, a10 = 0ull, a11 = 0ull;
#pragma unroll
            for (int kk = 0; kk < 16; kk += 4) {
                ulonglong2 v0 = *(const ulonglong2*)(ap + (size_t)(rs + 0) * 64 + kk);
                ulonglong2 v1 = *(const ulonglong2*)(ap + (size_t)(rs + 1) * 64 + kk);
                ffma2(a00, v0.x, w[0][kk / 2]); ffma2(a00, v0.y, w[0][kk / 2 + 1]);
                ffma2(a10, v0.x, w[1][kk / 2]); ffma2(a10, v0.y, w[1][kk / 2 + 1]);
                ffma2(a01, v1.x, w[0][kk / 2]); ffma2(a01, v1.y, w[0][kk / 2 + 1]);
                ffma2(a11, v1.x, w[1][kk / 2]); ffma2(a11, v1.y, w[1][kk / 2 + 1]);
            }
            gpA[(rs + 0) * 64] = hsum2(a00);
            gpA[(rs + 1) * 64] = hsum2(a01);
            gpB[(rs + 0) * 64] = hsum2(a10);
            gpB[(rs + 1) * 64] = hsum2(a11);
        };

        // ---- EW: rows [rs,...), nunits threads, 1 unit each; folds 8 q + bias ----
        auto ew_rows = [&](int rs, int nunits, int t) {
            if (tid < nunits) {
                const int r  = rs + (tid >> 6);
                const int uu = tid & 63;
                float gv[4];
#pragma unroll
                for (int c = 0; c < 4; c++) {
                    const float* gp = s_gp + (size_t)(c * 8) * RW + r * 64 + uu;
                    float s = s_bias[c * 64 + uu];
#pragma unroll
                    for (int qq = 0; qq < 8; qq++) s += gp[(size_t)qq * RW];
                    gv[c] = s;
                }
                float iv = sigm(gv[0]), fv = sigm(gv[1]), gg = tanh_(gv[2]), ov = sigm(gv[3]);
                float cc = fmaf(fv, s_c[r * 64 + uu], iv * gg);
                float hh = ov * tanh_(cc);
                s_c[r * 64 + uu] = cc;
                s_h[r * 64 + uu] = hh;
                out[((size_t)t * BP + b0 + r) * 64 + uu] = hh;
            }
        };

        // per-layer prologue: h0=c0=0; stage x(0), x(1); ML(0) rows 0-7
        for (int i = tid; i < RW; i += NTHR) { s_h[i] = 0.0f; s_c[i] = 0.0f; }
        __syncthreads();   // prev-layer gmem writes visible; h/c zeroed
        if (tid < BT * 16) {
            ((float4*)s_x)[tid]        = ((const float4*)(in + (size_t)b0 * 64))[tid];
            ((float4*)(s_x + RW))[tid] = ((const float4*)(in + ((size_t)BP + b0) * 64))[tid];
        }
        __syncthreads();
        {
            const float* ap0 = (q < 4) ? (s_x + q * 16) : (s_h + (q - 4) * 16);
            ml2(ap0, 0); ml2(ap0, 2); ml2(ap0, 4); ml2(ap0, 6);
        }
        __syncthreads();   // partials(0) rows 0-7 ready

        for (int t = 0; t < TT; t++) {
            const int cur = t & 1, nxt = cur ^ 1;
            const float* ap_cur = (q < 4) ? (s_x + cur * RW + q * 16)
                                          : (s_h + (q - 4) * 16);
            const float* ap_nxt = (q < 4) ? (s_x + nxt * RW + q * 16)
                                          : (s_h + (q - 4) * 16);

            // ---- P1: ML(t) rows 8-13 || EW(t) rows 0-7 ----
            ml2(ap_cur, 8); ml2(ap_cur, 10); ml2(ap_cur, 12);
            ew_rows(0, 512, t);
            asm volatile("cp.async.wait_group 0;" ::: "memory");  // x(t+1) landed
            __syncthreads();   // partials(t) rows 8-13 ready; h(t) rows 0-7 final

            // ---- P2: ML(t+1) rows 0-7 || EW(t) rows 8-13 || cp.async x(t+2) ----
            if (t + 1 < TT) {
                ml2(ap_nxt, 0); ml2(ap_nxt, 2); ml2(ap_nxt, 4); ml2(ap_nxt, 6);
            }
            ew_rows(8, 384, t);
            if (t + 2 < TT && tid < BT * 16) {
                // x(t) buffer (s_x[cur]) is dead after the P1 barrier -> refill
                cp_async16(sx_u32 + (uint32_t)(cur * RW + tid * 4) * 4,
                           (const float4*)(in + ((size_t)(t + 2) * BP + b0) * 64) + tid);
            }
            asm volatile("cp.async.commit_group;" ::: "memory");
            __syncthreads();   // partials(t+1) rows 0-7 ready; h(t) complete
        }
        cur_in ^= 1;
    }

    // ---- epilogue: output MLP for own rows ----
    if (tid < BT * TT) {
        const float* fin = cur_in ? g_bufB : g_bufA;
        int r = tid >> 6;
        int t = tid & 63;
        int b = b0 + r;
        if (b < BB) {
            float h[64];
            const float4* src = (const float4*)(fin + ((size_t)t * BP + b) * 64);
#pragma unroll
            for (int i = 0; i < 16; i++) {
                float4 v = src[i];
                h[4 * i + 0] = v.x; h[4 * i + 1] = v.y;
                h[4 * i + 2] = v.z; h[4 * i + 3] = v.w;
            }
            float h2[32];
#pragma unroll
            for (int j = 0; j < 32; j++) {
                float o = s_ob1[j];
#pragma unroll
                for (int k = 0; k < 64; k++) o = fmaf(s_ow1[j * 64 + k], h[k], o);
                h2[j] = fmaxf(o, 0.0f);
            }
            float o[4];
#pragma unroll
            for (int j = 0; j < 4; j++) {
                float s = s_ob2[j];
#pragma unroll
                for (int k = 0; k < 32; k++) s = fmaf(s_ow2[j * 32 + k], h2[k], s);
                o[j] = s;
            }
            *(float4*)(outp + ((size_t)b * TT + t) * 4) =
                make_float4(o[0], o[1], o[2], o[3]);
        }
    }
}

// ---------------------------------------------------------------------------
extern "C" void kernel_launch(void* const* d_in, const int* in_sizes, int n_in,
                              void* d_out, int out_size)
{
    const float* x     = (const float*)d_in[0];
    const float* w1    = (const float*)d_in[1];
    const float* b1    = (const float*)d_in[2];
    const float* w2    = (const float*)d_in[3];
    const float* b2    = (const float*)d_in[4];
    const float* w_ih0 = (const float*)d_in[5];
    const float* w_hh0 = (const float*)d_in[6];
    const float* b_ih0 = (const float*)d_in[7];
    const float* b_hh0 = (const float*)d_in[8];
    const float* w_ih  = (const float*)d_in[9];   // (7, 256, 64)
    const float* w_hh  = (const float*)d_in[10];  // (7, 256, 64)
    const float* b_ih  = (const float*)d_in[11];  // (7, 256)
    const float* b_hh  = (const float*)d_in[12];  // (7, 256)
    const float* wo1   = (const float*)d_in[13];
    const float* bo1   = (const float*)d_in[14];
    const float* wo2   = (const float*)d_in[15];
    const float* bo2   = (const float*)d_in[16];
    float* outp = (float*)d_out;

    // smem: x(2) + h + c + gp(32) planes + bias + mlp weights
    const int smem_sz = (36 * RW + 256 + 320 + 2048 + 32 + 128 + 4) * 4;  // 140176 B
    cudaFuncSetAttribute(model_kernel, cudaFuncAttributeMaxDynamicSharedMemorySize, smem_sz);

    model_kernel<<<NCTA, NTHR, smem_sz>>>(x, w1, b1, w2, b2,
                                          w_ih0, w_hh0, b_ih0, b_hh0,
                                          w_ih, w_hh, b_ih, b_hh,
                                          wo1, bo1, wo2, bo2, outp);
}

// round 17
// speedup vs baseline: 1.1102x; 1.1102x over previous
#include <cuda_runtime.h>
#include <cuda_bf16.h>
#include <cstdint>

// Problem constants
#define BB 2048   // batch
#define BP 2058   // padded batch (147 CTAs * 14 rows)
#define TT 64     // timesteps
#define HH 64     // LSTM hidden
#define GG 256    // 4*H gates
#define NL 8      // LSTM layers
#define BT 14     // batch rows per CTA
#define NCTA 147

// Ping-pong inter-layer buffers, layout [T, BP, 64] (layer0 x: cols 0-15, rest zero)
__device__ float g_bufA[(size_t)TT * BP * HH + 256];
__device__ float g_bufB[(size_t)TT * BP * HH + 256];

__device__ __forceinline__ float sigm(float x) {
    return __fdividef(1.0f, 1.0f + __expf(-x));
}
__device__ __forceinline__ float tanh_(float x) {
    return __fdividef(2.0f, 1.0f + __expf(-2.0f * x)) - 1.0f;
}

// ---- packed f32x2 helpers (Blackwell FFMA2; PTX-only) ----
__device__ __forceinline__ void ffma2(uint64_t& d, uint64_t a, uint64_t b) {
    asm("fma.rn.f32x2 %0, %1, %2, %0;" : "+l"(d) : "l"(a), "l"(b));
}
__device__ __forceinline__ uint64_t pack2(float lo, float hi) {
    uint64_t r;
    asm("mov.b64 %0, {%1, %2};" : "=l"(r) : "f"(lo), "f"(hi));
    return r;
}
__device__ __forceinline__ float hsum2(uint64_t v) {
    float lo, hi;
    asm("mov.b64 {%0, %1}, %2;" : "=f"(lo), "=f"(hi) : "l"(v));
    return lo + hi;
}

// ---------------------------------------------------------------------------
// Whole-model persistent kernel; 147 CTAs x 512 threads; each CTA owns 14
// batch rows end-to-end (input MLP -> 8 LSTM layers -> output MLP).
// Mapping: p = tid&127 (col pair jA=p -> gate glo, jB=p+128 -> gate 2+glo),
// q = tid>>7 (4 K-windows of 32: q<2 x ks, q>=2 h ks).
// Gate partials live interleaved: s_gp[gate][row][unit][4], the 4 q-lane
// slots XOR-swizzled by sw=(q+(u>>3))&3 so ML's STS.32 is bank-conflict-free
// per warp while EW folds each gate with ONE LDS.128 (sum is permutation-
// invariant, so the swizzle needs no unshuffle).
// Cross-step 2-barrier schedule (EW never exposed):
//   P1: ML(t) rows 8-13  || EW(t) rows 0-7                       -> bar
//   P2: ML(t+1) rows 0-7 || EW(t) rows 8-13 || x(t+2) commit     -> bar
// ---------------------------------------------------------------------------
__global__ void __launch_bounds__(512, 1)
model_kernel(const float* __restrict__ x_in,
             const float* __restrict__ w1, const float* __restrict__ b1,
             const float* __restrict__ w2, const float* __restrict__ b2,
             const float* __restrict__ w_ih0, const float* __restrict__ w_hh0,
             const float* __restrict__ b_ih0, const float* __restrict__ b_hh0,
             const float* __restrict__ w_ih, const float* __restrict__ w_hh,
             const float* __restrict__ b_ih, const float* __restrict__ b_hh,
             const float* __restrict__ wo1, const float* __restrict__ bo1,
             const float* __restrict__ wo2, const float* __restrict__ bo2,
             float* __restrict__ outp)
{
    extern __shared__ float smem[];
    float* s_x   = smem;                  // [2][BT*64]
    float* s_h   = s_x + 2 * BT * 64;     // [BT*64]
    float* s_c   = s_h + BT * 64;         // [BT*64]
    float* s_gp  = s_c + BT * 64;         // [4 gates][BT][64][4]  (16*BT*64 floats)
    float* s_mw  = s_gp + 16 * BT * 64;   // mlp-in w1[32],b1[16],w2[256],b2[16]
    float* s_ow1 = s_mw + 320;            // [32][64]
    float* s_ob1 = s_ow1 + 2048;          // [32]
    float* s_ow2 = s_ob1 + 32;            // [4][32]
    float* s_ob2 = s_ow2 + 128;           // [4]

    const int tid = threadIdx.x;
    const int p   = tid & 127;            // column pair
    const int q   = tid >> 7;             // K split 0..3
    const int b0  = blockIdx.x * BT;
    const int glo = p >> 6;               // gate of jA: 0=i, 1=f
    const int u   = p & 63;               // unit
    const int sw  = (q + (u >> 3)) & 3;   // conflict-free STS slot swizzle

    // ---- load MLP weights into smem ----
    if (tid < 32)  s_mw[tid] = w1[tid];
    if (tid < 16)  s_mw[32 + tid] = b1[tid];
    if (tid >= 64 && tid < 64 + 256) s_mw[48 + (tid - 64)] = w2[tid - 64];
    if (tid >= 320 && tid < 336) s_mw[304 + (tid - 320)] = b2[tid - 320];
    for (int i = tid; i < 2048; i += 512) s_ow1[i] = wo1[i];
    if (tid < 32) s_ob1[tid] = bo1[tid];
    if (tid < 128) s_ow2[tid] = wo2[tid];
    if (tid < 4) s_ob2[tid] = bo2[tid];
    __syncthreads();

    // ---- prologue: input MLP for own rows -> g_bufA[t][b0..b0+13][0..63] ----
    {
        const float* mw1 = s_mw;
        const float* mb1 = s_mw + 32;
        const float* mw2 = s_mw + 48;
        const float* mb2 = s_mw + 304;
        for (int pass = 0; pass < 2; pass++) {
            int idx = pass * 512 + tid;   // r*64 + t
            if (idx < BT * TT) {
                int r = idx >> 6;
                int t = idx & 63;
                int b = b0 + r;
                float x0 = 0.f, x1 = 0.f;
                if (b < BB) {
                    x0 = x_in[((size_t)b * TT + t) * 2 + 0];
                    x1 = x_in[((size_t)b * TT + t) * 2 + 1];
                }
                float h1[16];
#pragma unroll
                for (int j = 0; j < 16; j++) {
                    float v = fmaf(mw1[j * 2], x0, fmaf(mw1[j * 2 + 1], x1, mb1[j]));
                    h1[j] = fmaxf(v, 0.0f);
                }
                float o[16];
#pragma unroll
                for (int j = 0; j < 16; j++) {
                    float s = mb2[j];
#pragma unroll
                    for (int k = 0; k < 16; k++) s = fmaf(mw2[j * 16 + k], h1[k], s);
                    o[j] = s;
                }
                float4* dst = (float4*)(g_bufA + ((size_t)t * BP + b) * 64);
#pragma unroll
                for (int j = 0; j < 4; j++)
                    dst[j] = make_float4(o[4 * j], o[4 * j + 1], o[4 * j + 2], o[4 * j + 3]);
                float4 z = make_float4(0.f, 0.f, 0.f, 0.f);
#pragma unroll
                for (int j = 4; j < 16; j++) dst[j] = z;
            }
        }
    }

    // ---- layer loop ----
    int cur_in = 0;
    for (int l = 0; l < NL; l++) {
        const float* in  = cur_in ? g_bufB : g_bufA;
        float*       out = cur_in ? g_bufA : g_bufB;

        // load this layer's weights into regs (2 cols x 32 ks as u64 pairs)
        uint64_t w[2][16];
        uint64_t bias[2];
#pragma unroll
        for (int c = 0; c < 2; c++) {
            const int j = p + c * 128;
#pragma unroll
            for (int kk = 0; kk < 32; kk += 2) {
                float a, b;
                if (q < 2) {
                    int k = q * 32 + kk;
                    if (l == 0) {
                        a = (k < 16)     ? w_ih0[(size_t)j * 16 + k]     : 0.0f;
                        b = (k + 1 < 16) ? w_ih0[(size_t)j * 16 + k + 1] : 0.0f;
                    } else {
                        const float* wih = w_ih + (size_t)(l - 1) * GG * HH;
                        a = wih[(size_t)j * 64 + k];
                        b = wih[(size_t)j * 64 + k + 1];
                    }
                } else {
                    int k = (q - 2) * 32 + kk;
                    const float* whh = (l == 0) ? w_hh0 : w_hh + (size_t)(l - 1) * GG * HH;
                    a = whh[(size_t)j * 64 + k];
                    b = whh[(size_t)j * 64 + k + 1];
                }
                w[c][kk / 2] = pack2(a, b);
            }
            const float* bi = (l == 0) ? b_ih0 : b_ih + (size_t)(l - 1) * GG;
            const float* bh = (l == 0) ? b_hh0 : b_hh + (size_t)(l - 1) * GG;
            bias[c] = (q == 0) ? pack2(bi[j] + bh[j], 0.0f) : 0ull;
        }

        // partial slot base: gate c_gate at [c_gate][row][u][sw]
        float* gpA = s_gp + (size_t)(glo)     * BT * 64 * 4 + u * 4 + sw;
        float* gpB = s_gp + (size_t)(2 + glo) * BT * 64 * 4 + u * 4 + sw;

        // ---- ML chunk for given x-slot: rows [rs, rs+rn), rn <= 4 ----
        auto ml_rows = [&](const float* ap, int rs, int rn) {
            uint64_t accA[4], accB[4];
#pragma unroll
            for (int r = 0; r < 4; r++) { accA[r] = bias[0]; accB[r] = bias[1]; }
#pragma unroll
            for (int kk = 0; kk < 32; kk += 4) {
#pragma unroll
                for (int r = 0; r < 4; r++) {
                    if (r < rn) {
                        ulonglong2 v = *(const ulonglong2*)(ap + (size_t)(rs + r) * 64 + kk);
                        ffma2(accA[r], v.x, w[0][kk / 2]);
                        ffma2(accA[r], v.y, w[0][kk / 2 + 1]);
                        ffma2(accB[r], v.x, w[1][kk / 2]);
                        ffma2(accB[r], v.y, w[1][kk / 2 + 1]);
                    }
                }
            }
#pragma unroll
            for (int r = 0; r < 4; r++) {
                if (r < rn) {
                    gpA[(size_t)(rs + r) * 256] = hsum2(accA[r]);
                    gpB[(size_t)(rs + r) * 256] = hsum2(accB[r]);
                }
            }
        };

        // ---- EW: rows [rs,...), nunits threads, 1 unit each ----
        auto ew_rows = [&](int rs, int nunits, int t) {
            if (tid < nunits) {
                const int r  = rs + (tid >> 6);
                const int uu = tid & 63;
                float gv[4];
#pragma unroll
                for (int c = 0; c < 4; c++) {
                    float4 v = *(const float4*)(s_gp + ((size_t)c * BT * 64 + r * 64 + uu) * 4);
                    gv[c] = (v.x + v.y) + (v.z + v.w);
                }
                float iv = sigm(gv[0]), fv = sigm(gv[1]), gg = tanh_(gv[2]), ov = sigm(gv[3]);
                float cc = fmaf(fv, s_c[r * 64 + uu], iv * gg);
                float hh = ov * tanh_(cc);
                s_c[r * 64 + uu] = cc;
                s_h[r * 64 + uu] = hh;
                out[((size_t)t * BP + b0 + r) * 64 + uu] = hh;
            }
        };

        // per-layer prologue (merged): h0=c0=0 AND stage x(0) in one phase
        for (int i = tid; i < BT * 64; i += 512) { s_h[i] = 0.0f; s_c[i] = 0.0f; }
        if (tid < BT * 16)
            ((float4*)s_x)[tid] = ((const float4*)(in + (size_t)b0 * 64))[tid];
        __syncthreads();   // prev-layer gmem writes already fenced by loop-end bar
        {
            float4 pf1;
            if (tid < BT * 16)
                pf1 = ((const float4*)(in + ((size_t)BP + b0) * 64))[tid];
            const float* ap0 = (q < 2) ? (s_x + q * 32) : (s_h + (q - 2) * 32);
            ml_rows(ap0, 0, 4);
            ml_rows(ap0, 4, 4);
            if (tid < BT * 16)
                ((float4*)(s_x + BT * 64))[tid] = pf1;
        }
        __syncthreads();   // partials(0) rows 0-7 ready; x(1) staged

        for (int t = 0; t < TT; t++) {
            const int cur = t & 1, nxt = cur ^ 1;
            const float* ap_cur = (q < 2) ? (s_x + cur * BT * 64 + q * 32)
                                          : (s_h + (q - 2) * 32);
            const float* ap_nxt = (q < 2) ? (s_x + nxt * BT * 64 + q * 32)
                                          : (s_h + (q - 2) * 32);

            // prefetch x(t+2) into regs (hidden under P1)
            float4 pf;
            const bool do_pf = (t + 2 < TT) && (tid < BT * 16);
            if (do_pf)
                pf = ((const float4*)(in + ((size_t)(t + 2) * BP + b0) * 64))[tid];

            // ---- P1: ML(t) rows 8-13 || EW(t) rows 0-7 ----
            ml_rows(ap_cur, 8, 4);
            ml_rows(ap_cur, 12, 2);
            ew_rows(0, 512, t);
            __syncthreads();   // partials(t) rows 8-13 ready; h(t) rows 0-7 final

            // ---- P2: ML(t+1) rows 0-7 || EW(t) rows 8-13 || x(t+2) commit ----
            if (t + 1 < TT) {
                ml_rows(ap_nxt, 0, 4);
                ml_rows(ap_nxt, 4, 4);
            }
            ew_rows(8, 384, t);
            if (do_pf)
                ((float4*)(s_x + cur * BT * 64))[tid] = pf;   // x(t) dead
            __syncthreads();   // partials(t+1) rows 0-7 ready; h(t) complete
        }
        cur_in ^= 1;
    }

    // ---- epilogue: output MLP for own rows ----
    {
        const float* fin = cur_in ? g_bufB : g_bufA;
        for (int pass = 0; pass < 2; pass++) {
            int idx = pass * 512 + tid;      // r*64 + t
            if (idx < BT * TT) {
                int r = idx >> 6;
                int t = idx & 63;
                int b = b0 + r;
                if (b < BB) {
                    float h[64];
                    const float4* src = (const float4*)(fin + ((size_t)t * BP + b) * 64);
#pragma unroll
                    for (int i = 0; i < 16; i++) {
                        float4 v = src[i];
                        h[4 * i + 0] = v.x; h[4 * i + 1] = v.y;
                        h[4 * i + 2] = v.z; h[4 * i + 3] = v.w;
                    }
                    float h2[32];
#pragma unroll
                    for (int j = 0; j < 32; j++) {
                        float o = s_ob1[j];
#pragma unroll
                        for (int k = 0; k < 64; k++) o = fmaf(s_ow1[j * 64 + k], h[k], o);
                        h2[j] = fmaxf(o, 0.0f);
                    }
                    float o[4];
#pragma unroll
                    for (int j = 0; j < 4; j++) {
                        float s = s_ob2[j];
#pragma unroll
                        for (int k = 0; k < 32; k++) s = fmaf(s_ow2[j * 32 + k], h2[k], s);
                        o[j] = s;
                    }
                    *(float4*)(outp + ((size_t)b * TT + t) * 4) =
                        make_float4(o[0], o[1], o[2], o[3]);
                }
            }
        }
    }
}

// ---------------------------------------------------------------------------
extern "C" void kernel_launch(void* const* d_in, const int* in_sizes, int n_in,
                              void* d_out, int out_size)
{
    const float* x     = (const float*)d_in[0];
    const float* w1    = (const float*)d_in[1];
    const float* b1    = (const float*)d_in[2];
    const float* w2    = (const float*)d_in[3];
    const float* b2    = (const float*)d_in[4];
    const float* w_ih0 = (const float*)d_in[5];
    const float* w_hh0 = (const float*)d_in[6];
    const float* b_ih0 = (const float*)d_in[7];
    const float* b_hh0 = (const float*)d_in[8];
    const float* w_ih  = (const float*)d_in[9];   // (7, 256, 64)
    const float* w_hh  = (const float*)d_in[10];  // (7, 256, 64)
    const float* b_ih  = (const float*)d_in[11];  // (7, 256)
    const float* b_hh  = (const float*)d_in[12];  // (7, 256)
    const float* wo1   = (const float*)d_in[13];
    const float* bo1   = (const float*)d_in[14];
    const float* wo2   = (const float*)d_in[15];
    const float* bo2   = (const float*)d_in[16];
    float* outp = (float*)d_out;

    const int smem_sz = (20 * BT * 64 + 320 + 2048 + 32 + 128 + 4) * 4;  // 81808 B
    cudaFuncSetAttribute(model_kernel, cudaFuncAttributeMaxDynamicSharedMemorySize, smem_sz);

    model_kernel<<<NCTA, 512, smem_sz>>>(x, w1, b1, w2, b2,
                                         w_ih0, w_hh0, b_ih0, b_hh0,
                                         w_ih, w_hh, b_ih, b_hh,
                                         wo1, bo1, wo2, bo2, outp);
}